// round 5
// baseline (speedup 1.0000x reference)
#include <cuda_runtime.h>
#include <math.h>

#define B_ 8
#define NPTS 2048
#define KNB 10
#define KSEL 16
#define EPSV 1e-5f
#define MTOT (B_ * NPTS)

// ---------------- scratch (no allocation allowed) ----------------
__device__ float  d_x1[MTOT * 64];
__device__ float  d_x2[MTOT * 64];
__device__ float  d_x3[MTOT * 128];
__device__ float  d_x4[MTOT * 256];
__device__ float  d_yz[MTOT * 512];
__device__ int    d_idxbuf[MTOT * KNB];
__device__ int    d_cand[MTOT * KSEL];
__device__ double d_norm[MTOT];
__device__ float  d_wp[512 * 128];
__device__ float  d_part[B_ * 16 * 512];
__device__ float  d_gmax[B_ * 512];

// ---------------- helpers ----------------
template <int K>
__device__ __forceinline__ void insertK(float tv[K], int ti[K], float d, int m) {
    if (d <= tv[K - 1]) return;
    float cv = d; int ci = m;
#pragma unroll
    for (int p = 0; p < K; ++p) {
        if (cv > tv[p]) {
            float t = tv[p]; tv[p] = cv; cv = t;
            int u = ti[p]; ti[p] = ci; ci = u;
        }
    }
}

template <int K>
__device__ __forceinline__ void topk_merge_write(float tv[K], int ti[K],
                                                 int* __restrict__ out, int lane) {
    const unsigned FULL = 0xffffffffu;
#pragma unroll
    for (int r = 0; r < K; ++r) {
        float hv = tv[0]; int hi = ti[0];
        float v = hv; int i = hi;
#pragma unroll
        for (int off = 16; off; off >>= 1) {
            float ov = __shfl_down_sync(FULL, v, off);
            int   oi = __shfl_down_sync(FULL, i, off);
            if (ov > v || (ov == v && oi < i)) { v = ov; i = oi; }
        }
        float bv = __shfl_sync(FULL, v, 0);
        int   bi = __shfl_sync(FULL, i, 0);
        if (lane == 0) out[r] = bi;
        if (hv == bv && hi == bi) {  // this lane won: pop head
#pragma unroll
            for (int q = 0; q < K - 1; ++q) { tv[q] = tv[q + 1]; ti[q] = ti[q + 1]; }
            tv[K - 1] = -INFINITY; ti[K - 1] = 0x7fffffff;
        }
    }
}

// ---------------- fp64 point norms ----------------
__global__ void compute_norms(const float* __restrict__ x, double* __restrict__ nrm, int C) {
    int i = blockIdx.x * 256 + threadIdx.x;
    if (i < MTOT) {
        const float* p = x + (size_t)i * C;
        double s = 0.0;
        for (int c = 0; c < C; ++c) { double v = (double)p[c]; s += v * v; }
        nrm[i] = s;
    }
}

// ---------------- kNN pass 1 (fp32): warp handles 2 points, 32-point tiles, top-16 ----------------
template <int C>
__global__ void knn_kernel(const float* __restrict__ x, int* __restrict__ candout) {
    constexpr int PAD = (C % 4 == 0) ? 4 : 1;
    const int b = blockIdx.y;
    const int n0 = blockIdx.x * 16;
    const int tid = threadIdx.x;
    const int warp = tid >> 5, lane = tid & 31;

    __shared__ float s_cent[16][C];
    __shared__ float s_cn[16];
    __shared__ float s_tile[32][C + PAD];

    const float* xb = x + (size_t)b * NPTS * C;

    for (int i = tid; i < 16 * C; i += 256) {
        int p = i / C, c = i % C;
        s_cent[p][c] = xb[(size_t)(n0 + p) * C + c];
    }
    __syncthreads();
    if (tid < 16) {
        float s = 0.f;
        for (int c = 0; c < C; ++c) s += s_cent[tid][c] * s_cent[tid][c];
        s_cn[tid] = s;
    }
    __syncthreads();

    const int p0 = warp * 2, p1 = warp * 2 + 1;
    float tv0[KSEL], tv1[KSEL]; int ti0[KSEL], ti1[KSEL];
#pragma unroll
    for (int q = 0; q < KSEL; ++q) {
        tv0[q] = -INFINITY; tv1[q] = -INFINITY;
        ti0[q] = 0x7fffffff; ti1[q] = 0x7fffffff;
    }
    const float cn0 = s_cn[p0], cn1 = s_cn[p1];

    for (int m0 = 0; m0 < NPTS; m0 += 32) {
        __syncthreads();
        if (C % 4 == 0) {
            constexpr int C4 = C / 4;
            for (int i = tid; i < 32 * C4; i += 256) {
                int r = i / C4, c4 = i % C4;
                ((float4*)&s_tile[r][0])[c4] =
                    ((const float4*)&xb[(size_t)(m0 + r) * C])[c4];
            }
        } else {
            for (int i = tid; i < 32 * C; i += 256) {
                int r = i / C, c = i % C;
                s_tile[r][c] = xb[(size_t)(m0 + r) * C + c];
            }
        }
        __syncthreads();

        const int m = m0 + lane;
        float dot0 = 0.f, dot1 = 0.f, nm = 0.f;
        if (C % 4 == 0) {
#pragma unroll
            for (int c = 0; c < C; c += 4) {
                float4 t  = *(const float4*)&s_tile[lane][c];
                float4 c0 = *(const float4*)&s_cent[p0][c];
                float4 c1 = *(const float4*)&s_cent[p1][c];
                nm   += t.x * t.x + t.y * t.y + t.z * t.z + t.w * t.w;
                dot0 += c0.x * t.x + c0.y * t.y + c0.z * t.z + c0.w * t.w;
                dot1 += c1.x * t.x + c1.y * t.y + c1.z * t.z + c1.w * t.w;
            }
        } else {
#pragma unroll
            for (int c = 0; c < C; ++c) {
                float t = s_tile[lane][c];
                nm   += t * t;
                dot0 += s_cent[p0][c] * t;
                dot1 += s_cent[p1][c] * t;
            }
        }
        insertK<KSEL>(tv0, ti0, 2.f * dot0 - cn0 - nm, m);
        insertK<KSEL>(tv1, ti1, 2.f * dot1 - cn1 - nm, m);
    }

    topk_merge_write<KSEL>(tv0, ti0, candout + (size_t)(b * NPTS + n0 + p0) * KSEL, lane);
    topk_merge_write<KSEL>(tv1, ti1, candout + (size_t)(b * NPTS + n0 + p1) * KSEL, lane);
}

// ---------------- kNN pass 2: fp64 exact rescore of top-16, keep true top-10 ----------------
__global__ void rerank(const float* __restrict__ x, const double* __restrict__ nrm,
                       const int* __restrict__ cand, int* __restrict__ idxout, int C) {
    const unsigned FULL = 0xffffffffu;
    __shared__ float s_cent[8][128];
    const int warp = threadIdx.x >> 5, lane = threadIdx.x & 31;
    const int point = blockIdx.x * 8 + warp;          // global b*NPTS+n
    const int browbase = point & ~(NPTS - 1);
    const float* xb = x + (size_t)browbase * C;
    const int nloc = point - browbase;

    for (int c = lane; c < C; c += 32) s_cent[warp][c] = xb[(size_t)nloc * C + c];
    __syncwarp();

    double d = -INFINITY;
    int mi = 0x7fffffff;
    if (lane < KSEL) {
        mi = cand[(size_t)point * KSEL + lane];
        const float* row = xb + (size_t)mi * C;
        double dot = 0.0;
        for (int c = 0; c < C; ++c)
            dot += (double)s_cent[warp][c] * (double)row[c];
        d = 2.0 * dot - nrm[point] - nrm[browbase + mi];
    }

    int* out = idxout + (size_t)point * KNB;
#pragma unroll
    for (int r = 0; r < KNB; ++r) {
        double v = d; int i_ = mi;
#pragma unroll
        for (int off = 16; off; off >>= 1) {
            double ov = __shfl_down_sync(FULL, v, off);
            int    oi = __shfl_down_sync(FULL, i_, off);
            if (ov > v || (ov == v && oi < i_)) { v = ov; i_ = oi; }
        }
        double bv = __shfl_sync(FULL, v, 0);
        int    bi = __shfl_sync(FULL, i_, 0);
        if (lane == 0) out[r] = bi;
        if (d == bv && mi == bi) d = -INFINITY;
    }
}

// ---------------- weight prep: Wp = [A ; B - A] ----------------
__global__ void prep_w(const float* __restrict__ w, float* __restrict__ wp, int O, int C) {
    int i = blockIdx.x * 256 + threadIdx.x;
    if (i < O * C) {
        int o = i / C, c = i % C;
        float a = w[(size_t)o * 2 * C + c];
        wp[i] = a;
        wp[(size_t)O * C + i] = w[(size_t)o * 2 * C + C + c] - a;
    }
}

// ---------------- GEMM: Y[M,N] = X[M,K] * W[N,K]^T, 64x64 tiles, fp64 accumulate ----------------
__global__ void gemm64(const float* __restrict__ X, const float* __restrict__ W,
                       float* __restrict__ Y, int M, int K, int N) {
    __shared__ float sA[16][64];
    __shared__ float sB[16][64];
    const int tid = threadIdx.x;
    const int tx = tid & 15, ty = tid >> 4;
    const int m0 = blockIdx.y * 64, n0 = blockIdx.x * 64;
    double acc[4][4] = {};
    for (int kt = 0; kt < K; kt += 16) {
        for (int i = tid; i < 64 * 16; i += 256) {
            int r = i >> 4, kk = i & 15;
            int kg = kt + kk;
            sA[kk][r] = (kg < K) ? X[(size_t)(m0 + r) * K + kg] : 0.f;
            sB[kk][r] = (kg < K) ? W[(size_t)(n0 + r) * K + kg] : 0.f;
        }
        __syncthreads();
#pragma unroll
        for (int kk = 0; kk < 16; ++kk) {
            float4 a  = *(const float4*)&sA[kk][ty * 4];
            float4 bq = *(const float4*)&sB[kk][tx * 4];
            double av[4] = {a.x, a.y, a.z, a.w};
            double bv[4] = {bq.x, bq.y, bq.z, bq.w};
#pragma unroll
            for (int i2 = 0; i2 < 4; ++i2)
#pragma unroll
                for (int j2 = 0; j2 < 4; ++j2)
                    acc[i2][j2] += av[i2] * bv[j2];
        }
        __syncthreads();
    }
#pragma unroll
    for (int i2 = 0; i2 < 4; ++i2)
#pragma unroll
        for (int j2 = 0; j2 < 4; ++j2)
            Y[(size_t)(m0 + ty * 4 + i2) * N + n0 + tx * 4 + j2] = (float)acc[i2][j2];
}

// ---------------- gather + reduce + BN + lrelu ----------------
__global__ void edge_reduce(const float* __restrict__ yz, const int* __restrict__ idx,
                            const float* __restrict__ gg, const float* __restrict__ bb,
                            const float* __restrict__ rm, const float* __restrict__ rv,
                            float* __restrict__ xout, float* __restrict__ outT, int O) {
    const int bn = blockIdx.x;
    const int b = bn >> 11, n = bn & 2047;
    const int o = threadIdx.x;
    __shared__ int sj[KNB];
    if (o < KNB) sj[o] = idx[(size_t)bn * KNB + o];
    __syncthreads();
    const double scale = (double)gg[o] / sqrt((double)rv[o] + 1e-5);
    const int twoO = 2 * O;
    const float z = yz[(size_t)bn * twoO + O + o];
    const int browbase = b << 11;
    float red;
    if (scale >= 0.0) {
        red = -INFINITY;
#pragma unroll
        for (int j = 0; j < KNB; ++j)
            red = fmaxf(red, yz[(size_t)(browbase + sj[j]) * twoO + o]);
    } else {
        red = INFINITY;
#pragma unroll
        for (int j = 0; j < KNB; ++j)
            red = fminf(red, yz[(size_t)(browbase + sj[j]) * twoO + o]);
    }
    double h = (((double)red + (double)z) - (double)rm[o]) * scale + (double)bb[o];
    float hf = (float)h;
    float r = hf >= 0.f ? hf : 0.2f * hf;
    xout[(size_t)bn * O + o] = r;
    if (outT) outT[((size_t)b * O + o) * NPTS + n] = r;
}

// ---------------- global max (two pass) ----------------
__global__ void gmax_partial(const float* __restrict__ x1, const float* __restrict__ x2,
                             const float* __restrict__ x3, const float* __restrict__ x4,
                             float* __restrict__ part) {
    const int b = blockIdx.x, chunk = blockIdx.y;
    const int c = threadIdx.x;  // 0..511
    const float* src; int O, off;
    if (c < 64)       { src = x1; O = 64;  off = c; }
    else if (c < 128) { src = x2; O = 64;  off = c - 64; }
    else if (c < 256) { src = x3; O = 128; off = c - 128; }
    else              { src = x4; O = 256; off = c - 256; }
    float m = -INFINITY;
    const int nbeg = chunk * 128;
    const float* p = src + ((size_t)b * NPTS + nbeg) * O + off;
    for (int n = 0; n < 128; ++n) m = fmaxf(m, p[(size_t)n * O]);
    part[((size_t)b * 16 + chunk) * 512 + c] = m;
}

__global__ void gmax_final(const float* __restrict__ part, float* __restrict__ gmax) {
    const int b = blockIdx.x, c = threadIdx.x;
    float m = -INFINITY;
    for (int ch = 0; ch < 16; ++ch)
        m = fmaxf(m, part[((size_t)b * 16 + ch) * 512 + c]);
    gmax[(size_t)b * 512 + c] = m;
}

// ---------------- final FC + BN + lrelu (fp64 accumulate) ----------------
__global__ void final_fc(const float* __restrict__ gmax, const float* __restrict__ lw,
                         const float* __restrict__ lb, const float* __restrict__ g5,
                         const float* __restrict__ b5, const float* __restrict__ rm5,
                         const float* __restrict__ rv5, float* __restrict__ out) {
    const int b = blockIdx.y;
    const int o = blockIdx.x * 256 + threadIdx.x;
    __shared__ float sg[512];
    for (int i = threadIdx.x; i < 512; i += 256) sg[i] = gmax[(size_t)b * 512 + i];
    __syncthreads();
    const float* wrow = lw + (size_t)o * 512;
    double acc = 0.0;
#pragma unroll 8
    for (int c = 0; c < 512; ++c) acc += (double)sg[c] * (double)wrow[c];
    acc += (double)lb[o];
    const double scale = (double)g5[o] / sqrt((double)rv5[o] + 1e-5);
    double h = (acc - (double)rm5[o]) * scale + (double)b5[o];
    float hf = (float)h;
    out[(size_t)b * 1024 + o] = hf >= 0.f ? hf : 0.2f * hf;
}

// ---------------- launch ----------------
extern "C" void kernel_launch(void* const* d_in, const int* in_sizes, int n_in,
                              void* d_out, int out_size) {
    const float* x    = (const float*)d_in[0];
    const float* w1   = (const float*)d_in[1];
    const float* g1   = (const float*)d_in[2];
    const float* b1   = (const float*)d_in[3];
    const float* rm1  = (const float*)d_in[4];
    const float* rv1  = (const float*)d_in[5];
    const float* w2   = (const float*)d_in[6];
    const float* g2   = (const float*)d_in[7];
    const float* b2   = (const float*)d_in[8];
    const float* rm2  = (const float*)d_in[9];
    const float* rv2  = (const float*)d_in[10];
    const float* w3   = (const float*)d_in[11];
    const float* g3   = (const float*)d_in[12];
    const float* b3   = (const float*)d_in[13];
    const float* rm3  = (const float*)d_in[14];
    const float* rv3  = (const float*)d_in[15];
    const float* w4   = (const float*)d_in[16];
    const float* g4   = (const float*)d_in[17];
    const float* b4   = (const float*)d_in[18];
    const float* rm4  = (const float*)d_in[19];
    const float* rv4  = (const float*)d_in[20];
    const float* lw   = (const float*)d_in[21];
    const float* lb   = (const float*)d_in[22];
    const float* g5   = (const float*)d_in[23];
    const float* b5   = (const float*)d_in[24];
    const float* rm5  = (const float*)d_in[25];
    const float* rv5  = (const float*)d_in[26];

    float *x1, *x2, *x3, *x4, *yz, *wp, *part, *gmax;
    int *idx, *cand;
    double* nrm;
    cudaGetSymbolAddress((void**)&x1, d_x1);
    cudaGetSymbolAddress((void**)&x2, d_x2);
    cudaGetSymbolAddress((void**)&x3, d_x3);
    cudaGetSymbolAddress((void**)&x4, d_x4);
    cudaGetSymbolAddress((void**)&yz, d_yz);
    cudaGetSymbolAddress((void**)&idx, d_idxbuf);
    cudaGetSymbolAddress((void**)&cand, d_cand);
    cudaGetSymbolAddress((void**)&nrm, d_norm);
    cudaGetSymbolAddress((void**)&wp, d_wp);
    cudaGetSymbolAddress((void**)&part, d_part);
    cudaGetSymbolAddress((void**)&gmax, d_gmax);

    float* out = (float*)d_out;
    float* x4T = out + B_ * 1024;

    const dim3 knn_grid(NPTS / 16, B_);
    const int nrm_blocks = (MTOT + 255) / 256;
    const int rr_blocks = MTOT / 8;

    // layer 1: C=5 -> O=64
    compute_norms<<<nrm_blocks, 256>>>(x, nrm, 5);
    knn_kernel<5><<<knn_grid, 256>>>(x, cand);
    rerank<<<rr_blocks, 256>>>(x, nrm, cand, idx, 5);
    prep_w<<<(64 * 5 + 255) / 256, 256>>>(w1, wp, 64, 5);
    gemm64<<<dim3(128 / 64, MTOT / 64), 256>>>(x, wp, yz, MTOT, 5, 128);
    edge_reduce<<<MTOT, 64>>>(yz, idx, g1, b1, rm1, rv1, x1, nullptr, 64);

    // layer 2: C=64 -> O=64
    compute_norms<<<nrm_blocks, 256>>>(x1, nrm, 64);
    knn_kernel<64><<<knn_grid, 256>>>(x1, cand);
    rerank<<<rr_blocks, 256>>>(x1, nrm, cand, idx, 64);
    prep_w<<<(64 * 64 + 255) / 256, 256>>>(w2, wp, 64, 64);
    gemm64<<<dim3(128 / 64, MTOT / 64), 256>>>(x1, wp, yz, MTOT, 64, 128);
    edge_reduce<<<MTOT, 64>>>(yz, idx, g2, b2, rm2, rv2, x2, nullptr, 64);

    // layer 3: C=64 -> O=128
    compute_norms<<<nrm_blocks, 256>>>(x2, nrm, 64);
    knn_kernel<64><<<knn_grid, 256>>>(x2, cand);
    rerank<<<rr_blocks, 256>>>(x2, nrm, cand, idx, 64);
    prep_w<<<(128 * 64 + 255) / 256, 256>>>(w3, wp, 128, 64);
    gemm64<<<dim3(256 / 64, MTOT / 64), 256>>>(x2, wp, yz, MTOT, 64, 256);
    edge_reduce<<<MTOT, 128>>>(yz, idx, g3, b3, rm3, rv3, x3, nullptr, 128);

    // layer 4: C=128 -> O=256 (also writes transposed output)
    compute_norms<<<nrm_blocks, 256>>>(x3, nrm, 128);
    knn_kernel<128><<<knn_grid, 256>>>(x3, cand);
    rerank<<<rr_blocks, 256>>>(x3, nrm, cand, idx, 128);
    prep_w<<<(256 * 128 + 255) / 256, 256>>>(w4, wp, 256, 128);
    gemm64<<<dim3(512 / 64, MTOT / 64), 256>>>(x3, wp, yz, MTOT, 128, 512);
    edge_reduce<<<MTOT, 256>>>(yz, idx, g4, b4, rm4, rv4, x4, x4T, 256);

    // global max + final FC
    gmax_partial<<<dim3(B_, 16), 512>>>(x1, x2, x3, x4, part);
    gmax_final<<<B_, 512>>>(part, gmax);
    final_fc<<<dim3(4, B_), 256>>>(gmax, lw, lb, g5, b5, rm5, rv5, out);
}

// round 6
// speedup vs baseline: 2.1128x; 2.1128x over previous
#include <cuda_runtime.h>
#include <math.h>

#define B_ 8
#define NPTS 2048
#define KNB 10
#define KSEL 16
#define EPSV 1e-5f
#define MTOT (B_ * NPTS)

// ---------------- scratch (no allocation allowed) ----------------
__device__ float  d_x1[MTOT * 64];
__device__ float  d_x2[MTOT * 64];
__device__ float  d_x3[MTOT * 128];
__device__ float  d_x4[MTOT * 256];
__device__ float  d_yz[MTOT * 512];
__device__ int    d_idxbuf[MTOT * KNB];
__device__ int    d_cand[MTOT * KSEL];
__device__ double d_norm[MTOT];
__device__ float  d_wp[512 * 128];
__device__ float  d_part[B_ * 16 * 512];
__device__ float  d_gmax[B_ * 512];

// ---------------- helpers ----------------
template <int K>
__device__ __forceinline__ void insertK(float tv[K], int ti[K], float d, int m) {
    if (d <= tv[K - 1]) return;
    float cv = d; int ci = m;
#pragma unroll
    for (int p = 0; p < K; ++p) {
        if (cv > tv[p]) {
            float t = tv[p]; tv[p] = cv; cv = t;
            int u = ti[p]; ti[p] = ci; ci = u;
        }
    }
}

template <int K>
__device__ __forceinline__ void topk_merge_write(float tv[K], int ti[K],
                                                 int* __restrict__ out, int lane) {
    const unsigned FULL = 0xffffffffu;
#pragma unroll
    for (int r = 0; r < K; ++r) {
        float hv = tv[0]; int hi = ti[0];
        float v = hv; int i = hi;
#pragma unroll
        for (int off = 16; off; off >>= 1) {
            float ov = __shfl_down_sync(FULL, v, off);
            int   oi = __shfl_down_sync(FULL, i, off);
            if (ov > v || (ov == v && oi < i)) { v = ov; i = oi; }
        }
        float bv = __shfl_sync(FULL, v, 0);
        int   bi = __shfl_sync(FULL, i, 0);
        if (lane == 0) out[r] = bi;
        if (hv == bv && hi == bi) {  // this lane won: pop head
#pragma unroll
            for (int q = 0; q < K - 1; ++q) { tv[q] = tv[q + 1]; ti[q] = ti[q + 1]; }
            tv[K - 1] = -INFINITY; ti[K - 1] = 0x7fffffff;
        }
    }
}

// ---------------- fp64 point norms: one warp per point ----------------
template <int C>
__global__ void compute_norms(const float* __restrict__ x, double* __restrict__ nrm) {
    const unsigned FULL = 0xffffffffu;
    const int gw = (blockIdx.x * 256 + threadIdx.x) >> 5;
    const int lane = threadIdx.x & 31;
    if (gw >= MTOT) return;
    const float* p = x + (size_t)gw * C;
    double s = 0.0;
#pragma unroll
    for (int c = lane; c < C; c += 32) { double v = (double)p[c]; s += v * v; }
#pragma unroll
    for (int off = 16; off; off >>= 1) s += __shfl_down_sync(FULL, s, off);
    if (lane == 0) nrm[gw] = s;
}

// ---------------- kNN pass 1 (fp32): warp handles 2 points, 32-point tiles, top-16 ----------------
template <int C>
__global__ void __launch_bounds__(256, 2)
knn_kernel(const float* __restrict__ x, int* __restrict__ candout) {
    constexpr int PAD = (C % 4 == 0) ? 4 : 1;
    const unsigned FULL = 0xffffffffu;
    const int b = blockIdx.y;
    const int n0 = blockIdx.x * 16;
    const int tid = threadIdx.x;
    const int warp = tid >> 5, lane = tid & 31;

    __shared__ float s_cent[16][C];
    __shared__ float s_cn[16];
    __shared__ float s_tile[32][C + PAD];
    __shared__ float s_nm[32];

    const float* xb = x + (size_t)b * NPTS * C;

    for (int i = tid; i < 16 * C; i += 256) {
        int p = i / C, c = i % C;
        s_cent[p][c] = xb[(size_t)(n0 + p) * C + c];
    }
    __syncthreads();
    if (tid < 16) {
        float s = 0.f;
        for (int c = 0; c < C; ++c) s += s_cent[tid][c] * s_cent[tid][c];
        s_cn[tid] = s;
    }
    __syncthreads();

    const int p0 = warp * 2, p1 = warp * 2 + 1;
    float tv0[KSEL], tv1[KSEL]; int ti0[KSEL], ti1[KSEL];
#pragma unroll
    for (int q = 0; q < KSEL; ++q) {
        tv0[q] = -INFINITY; tv1[q] = -INFINITY;
        ti0[q] = 0x7fffffff; ti1[q] = 0x7fffffff;
    }
    const float cn0 = s_cn[p0], cn1 = s_cn[p1];

    for (int m0 = 0; m0 < NPTS; m0 += 32) {
        __syncthreads();
        if (C % 4 == 0) {
            // fused tile load + per-row norm (subgroup shuffle reduce)
            constexpr int C4 = C / 4;
#pragma unroll
            for (int i = tid; i < 32 * C4; i += 256) {
                int r = i / C4, c4 = i % C4;
                float4 t = ((const float4*)&xb[(size_t)(m0 + r) * C])[c4];
                ((float4*)&s_tile[r][0])[c4] = t;
                float pn = t.x * t.x + t.y * t.y + t.z * t.z + t.w * t.w;
#pragma unroll
                for (int off = C4 / 2; off; off >>= 1)
                    pn += __shfl_down_sync(FULL, pn, off, C4);
                if ((tid & (C4 - 1)) == 0) s_nm[r] = pn;
            }
        } else {
            for (int i = tid; i < 32 * C; i += 256) {
                int r = i / C, c = i % C;
                s_tile[r][c] = xb[(size_t)(m0 + r) * C + c];
            }
        }
        __syncthreads();

        const int m = m0 + lane;
        float dot0 = 0.f, dot1 = 0.f;
        float nm;
        if (C % 4 == 0) {
            nm = s_nm[lane];
#pragma unroll
            for (int c = 0; c < C; c += 4) {
                float4 t  = *(const float4*)&s_tile[lane][c];
                float4 c0 = *(const float4*)&s_cent[p0][c];
                float4 c1 = *(const float4*)&s_cent[p1][c];
                dot0 += c0.x * t.x + c0.y * t.y + c0.z * t.z + c0.w * t.w;
                dot1 += c1.x * t.x + c1.y * t.y + c1.z * t.z + c1.w * t.w;
            }
        } else {
            nm = 0.f;
#pragma unroll
            for (int c = 0; c < C; ++c) {
                float t = s_tile[lane][c];
                nm   += t * t;
                dot0 += s_cent[p0][c] * t;
                dot1 += s_cent[p1][c] * t;
            }
        }
        insertK<KSEL>(tv0, ti0, 2.f * dot0 - cn0 - nm, m);
        insertK<KSEL>(tv1, ti1, 2.f * dot1 - cn1 - nm, m);
    }

    topk_merge_write<KSEL>(tv0, ti0, candout + (size_t)(b * NPTS + n0 + p0) * KSEL, lane);
    topk_merge_write<KSEL>(tv1, ti1, candout + (size_t)(b * NPTS + n0 + p1) * KSEL, lane);
}

// ---------------- kNN pass 2: fp64 exact rescore of top-16, keep true top-10 ----------------
template <int C>
__global__ void rerank(const float* __restrict__ x, const double* __restrict__ nrm,
                       const int* __restrict__ cand, int* __restrict__ idxout) {
    const unsigned FULL = 0xffffffffu;
    __shared__ float s_cent[8][C];
    const int warp = threadIdx.x >> 5, lane = threadIdx.x & 31;
    const int point = blockIdx.x * 8 + warp;          // global b*NPTS+n
    const int browbase = point & ~(NPTS - 1);
    const float* xb = x + (size_t)browbase * C;
    const int nloc = point - browbase;

    for (int c = lane; c < C; c += 32) s_cent[warp][c] = xb[(size_t)nloc * C + c];
    __syncwarp();

    double d = -INFINITY;
    int mi = 0x7fffffff;
    if (lane < KSEL) {
        mi = cand[(size_t)point * KSEL + lane];
        const float* row = xb + (size_t)mi * C;
        if (C % 4 == 0) {
            double a0 = 0.0, a1 = 0.0, a2 = 0.0, a3 = 0.0;
#pragma unroll
            for (int c = 0; c < C; c += 4) {
                float4 r = *(const float4*)&row[c];
                a0 += (double)s_cent[warp][c + 0] * (double)r.x;
                a1 += (double)s_cent[warp][c + 1] * (double)r.y;
                a2 += (double)s_cent[warp][c + 2] * (double)r.z;
                a3 += (double)s_cent[warp][c + 3] * (double)r.w;
            }
            d = 2.0 * ((a0 + a1) + (a2 + a3)) - nrm[point] - nrm[browbase + mi];
        } else {
            double dot = 0.0;
#pragma unroll
            for (int c = 0; c < C; ++c)
                dot += (double)s_cent[warp][c] * (double)row[c];
            d = 2.0 * dot - nrm[point] - nrm[browbase + mi];
        }
    }

    int* out = idxout + (size_t)point * KNB;
#pragma unroll
    for (int r = 0; r < KNB; ++r) {
        double v = d; int i_ = mi;
#pragma unroll
        for (int off = 16; off; off >>= 1) {
            double ov = __shfl_down_sync(FULL, v, off);
            int    oi = __shfl_down_sync(FULL, i_, off);
            if (ov > v || (ov == v && oi < i_)) { v = ov; i_ = oi; }
        }
        double bv = __shfl_sync(FULL, v, 0);
        int    bi = __shfl_sync(FULL, i_, 0);
        if (lane == 0) out[r] = bi;
        if (d == bv && mi == bi) d = -INFINITY;
    }
}

// ---------------- weight prep: Wp = [A ; B - A] ----------------
__global__ void prep_w(const float* __restrict__ w, float* __restrict__ wp, int O, int C) {
    int i = blockIdx.x * 256 + threadIdx.x;
    if (i < O * C) {
        int o = i / C, c = i % C;
        float a = w[(size_t)o * 2 * C + c];
        wp[i] = a;
        wp[(size_t)O * C + i] = w[(size_t)o * 2 * C + C + c] - a;
    }
}

// ---------------- GEMM: Y[M,N] = X[M,K] * W[N,K]^T, 64x64 tiles, fp32 ----------------
__global__ void gemm64(const float* __restrict__ X, const float* __restrict__ W,
                       float* __restrict__ Y, int M, int K, int N) {
    __shared__ float sA[16][64];
    __shared__ float sB[16][64];
    const int tid = threadIdx.x;
    const int tx = tid & 15, ty = tid >> 4;
    const int m0 = blockIdx.y * 64, n0 = blockIdx.x * 64;
    float acc[4][4] = {};
    for (int kt = 0; kt < K; kt += 16) {
        for (int i = tid; i < 64 * 16; i += 256) {
            int r = i >> 4, kk = i & 15;
            int kg = kt + kk;
            sA[kk][r] = (kg < K) ? X[(size_t)(m0 + r) * K + kg] : 0.f;
            sB[kk][r] = (kg < K) ? W[(size_t)(n0 + r) * K + kg] : 0.f;
        }
        __syncthreads();
#pragma unroll
        for (int kk = 0; kk < 16; ++kk) {
            float4 a  = *(const float4*)&sA[kk][ty * 4];
            float4 bq = *(const float4*)&sB[kk][tx * 4];
            float av[4] = {a.x, a.y, a.z, a.w};
            float bv[4] = {bq.x, bq.y, bq.z, bq.w};
#pragma unroll
            for (int i2 = 0; i2 < 4; ++i2)
#pragma unroll
                for (int j2 = 0; j2 < 4; ++j2)
                    acc[i2][j2] += av[i2] * bv[j2];
        }
        __syncthreads();
    }
#pragma unroll
    for (int i2 = 0; i2 < 4; ++i2)
#pragma unroll
        for (int j2 = 0; j2 < 4; ++j2)
            Y[(size_t)(m0 + ty * 4 + i2) * N + n0 + tx * 4 + j2] = acc[i2][j2];
}

// ---------------- gather + reduce + BN + lrelu ----------------
__global__ void edge_reduce(const float* __restrict__ yz, const int* __restrict__ idx,
                            const float* __restrict__ gg, const float* __restrict__ bb,
                            const float* __restrict__ rm, const float* __restrict__ rv,
                            float* __restrict__ xout, float* __restrict__ outT, int O) {
    const int bn = blockIdx.x;
    const int b = bn >> 11, n = bn & 2047;
    const int o = threadIdx.x;
    __shared__ int sj[KNB];
    if (o < KNB) sj[o] = idx[(size_t)bn * KNB + o];
    __syncthreads();
    const double scale = (double)gg[o] / sqrt((double)rv[o] + 1e-5);
    const int twoO = 2 * O;
    const float z = yz[(size_t)bn * twoO + O + o];
    const int browbase = b << 11;
    float red;
    if (scale >= 0.0) {
        red = -INFINITY;
#pragma unroll
        for (int j = 0; j < KNB; ++j)
            red = fmaxf(red, yz[(size_t)(browbase + sj[j]) * twoO + o]);
    } else {
        red = INFINITY;
#pragma unroll
        for (int j = 0; j < KNB; ++j)
            red = fminf(red, yz[(size_t)(browbase + sj[j]) * twoO + o]);
    }
    double h = (((double)red + (double)z) - (double)rm[o]) * scale + (double)bb[o];
    float hf = (float)h;
    float r = hf >= 0.f ? hf : 0.2f * hf;
    xout[(size_t)bn * O + o] = r;
    if (outT) outT[((size_t)b * O + o) * NPTS + n] = r;
}

// ---------------- global max (two pass) ----------------
__global__ void gmax_partial(const float* __restrict__ x1, const float* __restrict__ x2,
                             const float* __restrict__ x3, const float* __restrict__ x4,
                             float* __restrict__ part) {
    const int b = blockIdx.x, chunk = blockIdx.y;
    const int c = threadIdx.x;  // 0..511
    const float* src; int O, off;
    if (c < 64)       { src = x1; O = 64;  off = c; }
    else if (c < 128) { src = x2; O = 64;  off = c - 64; }
    else if (c < 256) { src = x3; O = 128; off = c - 128; }
    else              { src = x4; O = 256; off = c - 256; }
    float m = -INFINITY;
    const int nbeg = chunk * 128;
    const float* p = src + ((size_t)b * NPTS + nbeg) * O + off;
    for (int n = 0; n < 128; ++n) m = fmaxf(m, p[(size_t)n * O]);
    part[((size_t)b * 16 + chunk) * 512 + c] = m;
}

__global__ void gmax_final(const float* __restrict__ part, float* __restrict__ gmax) {
    const int b = blockIdx.x, c = threadIdx.x;
    float m = -INFINITY;
    for (int ch = 0; ch < 16; ++ch)
        m = fmaxf(m, part[((size_t)b * 16 + ch) * 512 + c]);
    gmax[(size_t)b * 512 + c] = m;
}

// ---------------- final FC + BN + lrelu (fp64 accumulate) ----------------
__global__ void final_fc(const float* __restrict__ gmax, const float* __restrict__ lw,
                         const float* __restrict__ lb, const float* __restrict__ g5,
                         const float* __restrict__ b5, const float* __restrict__ rm5,
                         const float* __restrict__ rv5, float* __restrict__ out) {
    const int b = blockIdx.y;
    const int o = blockIdx.x * 256 + threadIdx.x;
    __shared__ float sg[512];
    for (int i = threadIdx.x; i < 512; i += 256) sg[i] = gmax[(size_t)b * 512 + i];
    __syncthreads();
    const float* wrow = lw + (size_t)o * 512;
    double acc = 0.0;
#pragma unroll 8
    for (int c = 0; c < 512; ++c) acc += (double)sg[c] * (double)wrow[c];
    acc += (double)lb[o];
    const double scale = (double)g5[o] / sqrt((double)rv5[o] + 1e-5);
    double h = (acc - (double)rm5[o]) * scale + (double)b5[o];
    float hf = (float)h;
    out[(size_t)b * 1024 + o] = hf >= 0.f ? hf : 0.2f * hf;
}

// ---------------- launch ----------------
extern "C" void kernel_launch(void* const* d_in, const int* in_sizes, int n_in,
                              void* d_out, int out_size) {
    const float* x    = (const float*)d_in[0];
    const float* w1   = (const float*)d_in[1];
    const float* g1   = (const float*)d_in[2];
    const float* b1   = (const float*)d_in[3];
    const float* rm1  = (const float*)d_in[4];
    const float* rv1  = (const float*)d_in[5];
    const float* w2   = (const float*)d_in[6];
    const float* g2   = (const float*)d_in[7];
    const float* b2   = (const float*)d_in[8];
    const float* rm2  = (const float*)d_in[9];
    const float* rv2  = (const float*)d_in[10];
    const float* w3   = (const float*)d_in[11];
    const float* g3   = (const float*)d_in[12];
    const float* b3   = (const float*)d_in[13];
    const float* rm3  = (const float*)d_in[14];
    const float* rv3  = (const float*)d_in[15];
    const float* w4   = (const float*)d_in[16];
    const float* g4   = (const float*)d_in[17];
    const float* b4   = (const float*)d_in[18];
    const float* rm4  = (const float*)d_in[19];
    const float* rv4  = (const float*)d_in[20];
    const float* lw   = (const float*)d_in[21];
    const float* lb   = (const float*)d_in[22];
    const float* g5   = (const float*)d_in[23];
    const float* b5   = (const float*)d_in[24];
    const float* rm5  = (const float*)d_in[25];
    const float* rv5  = (const float*)d_in[26];

    float *x1, *x2, *x3, *x4, *yz, *wp, *part, *gmax;
    int *idx, *cand;
    double* nrm;
    cudaGetSymbolAddress((void**)&x1, d_x1);
    cudaGetSymbolAddress((void**)&x2, d_x2);
    cudaGetSymbolAddress((void**)&x3, d_x3);
    cudaGetSymbolAddress((void**)&x4, d_x4);
    cudaGetSymbolAddress((void**)&yz, d_yz);
    cudaGetSymbolAddress((void**)&idx, d_idxbuf);
    cudaGetSymbolAddress((void**)&cand, d_cand);
    cudaGetSymbolAddress((void**)&nrm, d_norm);
    cudaGetSymbolAddress((void**)&wp, d_wp);
    cudaGetSymbolAddress((void**)&part, d_part);
    cudaGetSymbolAddress((void**)&gmax, d_gmax);

    float* out = (float*)d_out;
    float* x4T = out + B_ * 1024;

    const dim3 knn_grid(NPTS / 16, B_);
    const int nrm_blocks = (MTOT * 32 + 255) / 256;
    const int rr_blocks = MTOT / 8;

    // layer 1: C=5 -> O=64
    compute_norms<5><<<nrm_blocks, 256>>>(x, nrm);
    knn_kernel<5><<<knn_grid, 256>>>(x, cand);
    rerank<5><<<rr_blocks, 256>>>(x, nrm, cand, idx);
    prep_w<<<(64 * 5 + 255) / 256, 256>>>(w1, wp, 64, 5);
    gemm64<<<dim3(128 / 64, MTOT / 64), 256>>>(x, wp, yz, MTOT, 5, 128);
    edge_reduce<<<MTOT, 64>>>(yz, idx, g1, b1, rm1, rv1, x1, nullptr, 64);

    // layer 2: C=64 -> O=64
    compute_norms<64><<<nrm_blocks, 256>>>(x1, nrm);
    knn_kernel<64><<<knn_grid, 256>>>(x1, cand);
    rerank<64><<<rr_blocks, 256>>>(x1, nrm, cand, idx);
    prep_w<<<(64 * 64 + 255) / 256, 256>>>(w2, wp, 64, 64);
    gemm64<<<dim3(128 / 64, MTOT / 64), 256>>>(x1, wp, yz, MTOT, 64, 128);
    edge_reduce<<<MTOT, 64>>>(yz, idx, g2, b2, rm2, rv2, x2, nullptr, 64);

    // layer 3: C=64 -> O=128
    compute_norms<64><<<nrm_blocks, 256>>>(x2, nrm);
    knn_kernel<64><<<knn_grid, 256>>>(x2, cand);
    rerank<64><<<rr_blocks, 256>>>(x2, nrm, cand, idx);
    prep_w<<<(128 * 64 + 255) / 256, 256>>>(w3, wp, 128, 64);
    gemm64<<<dim3(256 / 64, MTOT / 64), 256>>>(x2, wp, yz, MTOT, 64, 256);
    edge_reduce<<<MTOT, 128>>>(yz, idx, g3, b3, rm3, rv3, x3, nullptr, 128);

    // layer 4: C=128 -> O=256 (also writes transposed output)
    compute_norms<128><<<nrm_blocks, 256>>>(x3, nrm);
    knn_kernel<128><<<knn_grid, 256>>>(x3, cand);
    rerank<128><<<rr_blocks, 256>>>(x3, nrm, cand, idx);
    prep_w<<<(256 * 128 + 255) / 256, 256>>>(w4, wp, 256, 128);
    gemm64<<<dim3(512 / 64, MTOT / 64), 256>>>(x3, wp, yz, MTOT, 128, 512);
    edge_reduce<<<MTOT, 256>>>(yz, idx, g4, b4, rm4, rv4, x4, x4T, 256);

    // global max + final FC
    gmax_partial<<<dim3(B_, 16), 512>>>(x1, x2, x3, x4, part);
    gmax_final<<<B_, 512>>>(part, gmax);
    final_fc<<<dim3(4, B_), 256>>>(gmax, lw, lb, g5, b5, rm5, rv5, out);
}